// round 7
// baseline (speedup 1.0000x reference)
#include <cuda_runtime.h>
#include <math.h>

// Problem constants
#define B_    16
#define C_    64
#define H_    224
#define W_    224
#define HW_   (H_ * W_)          // 50176
#define HW4_  (HW_ / 4)          // 12544
#define CHW4_ ((C_ * HW_) / 4)   // 802816
#define ROW4  56                 // float4 per row (224/4)

// Device-global scratch (no allocation allowed)
__device__ float g_avg[B_ * HW_];            // 3.2 MB
__device__ float g_max[B_ * HW_];            // 3.2 MB
__device__ unsigned int g_flags[B_ * H_];    // per-row "feat ready" flags

// Dynamic smem layout (bytes):
//   [0 .. 57344)           x_s     : float4[64*56]  (the CTA's x row, all channels)
//   [57344 .. 57344+12992) scratch : phase1 = psum[4][56]+pmax[4][56] (7168B)
//                                    phase3 = halo[2][7][232] (12992B)
#define XS_F4      (C_ * ROW4)               // 3584 float4
#define SCRATCH_B  12992
#define DYN_SMEM   (XS_F4 * 16 + SCRATCH_B)  // 70336 bytes

// ---------------------------------------------------------------------------
// Kernel 0: reset flags (must run every launch; device globals persist).
// ---------------------------------------------------------------------------
__global__ void reset_flags_kernel() {
    int i = blockIdx.x * blockDim.x + threadIdx.x;
    if (i < B_ * H_) g_flags[i] = 0u;
}

// ---------------------------------------------------------------------------
// Main kernel: one CTA = (batch, row). Single DRAM pass over x.
// ---------------------------------------------------------------------------
__global__ void __launch_bounds__(256) fused_pipe_kernel(
        const float* __restrict__ x,
        const float* __restrict__ conv_w,
        const float* __restrict__ conv_b,
        float* __restrict__ out) {
    extern __shared__ float4 smem4[];
    float4* x_s     = smem4;                         // [64][56]
    float*  scratch = (float*)(smem4 + XS_F4);       // 12992 B

    __shared__ float s_gate[W_];
    __shared__ float s_w[98];

    int t   = threadIdx.x;                 // 0..255
    int bid = blockIdx.x;                  // b*H_ + h  (deps are bid +/- 1..3)
    int b   = bid / H_;
    int h   = bid - b * H_;

    if (t < 98) s_w[t] = conv_w[t];

    const float4* x4 = (const float4*)x + (long)b * CHW4_ + h * ROW4;

    // ---- Phase 1: stream own row (64 ch) into smem + partial channel reduce
    float4* psum = (float4*)scratch;       // [4][56]
    float4* pmax = psum + 4 * ROW4;        // [4][56]
    if (t < 224) {
        int cg = t / ROW4;                 // 0..3  (16 channels each)
        int p  = t - cg * ROW4;            // 0..55
        float4 s = make_float4(0.f, 0.f, 0.f, 0.f);
        float4 m = make_float4(-INFINITY, -INFINITY, -INFINITY, -INFINITY);
#pragma unroll
        for (int k = 0; k < 16; k++) {
            int c = cg * 16 + k;
            float4 v = __ldcs(&x4[(long)c * HW4_ + p]);   // evict-first read
            x_s[c * ROW4 + p] = v;
            s.x += v.x; s.y += v.y; s.z += v.z; s.w += v.w;
            m.x = fmaxf(m.x, v.x); m.y = fmaxf(m.y, v.y);
            m.z = fmaxf(m.z, v.z); m.w = fmaxf(m.w, v.w);
        }
        psum[cg * ROW4 + p] = s;
        pmax[cg * ROW4 + p] = m;
    }
    __syncthreads();

    // finalize feat row (56 threads), write to global (keep L2-resident)
    if (t < ROW4) {
        float4 s0 = psum[t], s1 = psum[ROW4 + t],
               s2 = psum[2 * ROW4 + t], s3 = psum[3 * ROW4 + t];
        float4 m0 = pmax[t], m1 = pmax[ROW4 + t],
               m2 = pmax[2 * ROW4 + t], m3 = pmax[3 * ROW4 + t];
        const float inv = 1.0f / (float)C_;
        float4 a, m;
        a.x = (s0.x + s1.x + s2.x + s3.x) * inv;
        a.y = (s0.y + s1.y + s2.y + s3.y) * inv;
        a.z = (s0.z + s1.z + s2.z + s3.z) * inv;
        a.w = (s0.w + s1.w + s2.w + s3.w) * inv;
        m.x = fmaxf(fmaxf(m0.x, m1.x), fmaxf(m2.x, m3.x));
        m.y = fmaxf(fmaxf(m0.y, m1.y), fmaxf(m2.y, m3.y));
        m.z = fmaxf(fmaxf(m0.z, m1.z), fmaxf(m2.z, m3.z));
        m.w = fmaxf(fmaxf(m0.w, m1.w), fmaxf(m2.w, m3.w));
        ((float4*)g_avg)[b * HW4_ + h * ROW4 + t] = a;
        ((float4*)g_max)[b * HW4_ + h * ROW4 + t] = m;
    }
    __syncthreads();
    if (t == 0) {
        __threadfence();                   // feat visible before flag
        atomicExch(&g_flags[bid], 1u);
    }

    // ---- Phase 2: wait for neighbor rows' feat (h-3..h+3, skip own)
    if (t < 7 && t != 3) {
        int hh = h - 3 + t;
        if (hh >= 0 && hh < H_) {
            while (atomicAdd(&g_flags[b * H_ + hh], 0u) == 0u)
                __nanosleep(64);
            __threadfence();               // acquire: order feat reads
        }
    }
    __syncthreads();

    // ---- Phase 3: halo load (2ch x 7r x 230c) + 7x7 conv + sigmoid
    float* halo = scratch;                 // reuse (psum/pmax dead); [2][7][232]
    for (int i = t; i < 2 * 7 * 230; i += 256) {
        int ch = i / (7 * 230);
        int rr = i - ch * (7 * 230);
        int r  = rr / 230;
        int hc = rr - r * 230;
        int hh = h - 3 + r;
        int gw = hc - 3;
        float v = 0.f;
        if (hh >= 0 && hh < H_ && gw >= 0 && gw < W_)
            v = (ch ? g_max : g_avg)[b * HW_ + hh * W_ + gw];
        halo[(ch * 7 + r) * 232 + hc] = v;
    }
    __syncthreads();

    if (t < W_) {
        float acc = conv_b[0];
#pragma unroll
        for (int ch = 0; ch < 2; ch++)
#pragma unroll
            for (int kh = 0; kh < 7; kh++) {
                const float* rp = halo + (ch * 7 + kh) * 232 + t;
                const float* wk = s_w + ch * 49 + kh * 7;
#pragma unroll
                for (int kw = 0; kw < 7; kw++)
                    acc = fmaf(rp[kw], wk[kw], acc);
            }
        s_gate[t] = 1.0f / (1.0f + __expf(-acc));
    }
    __syncthreads();

    // ---- Phase 4: multiply smem-cached x row by gates, stream out
    float4* o4 = (float4*)out + (long)b * CHW4_ + h * ROW4;
    for (int i = t; i < XS_F4; i += 256) {
        int c = i / ROW4;
        int p = i - c * ROW4;
        float4 v = x_s[i];
        float4 g = *(const float4*)(s_gate + 4 * p);
        v.x *= g.x; v.y *= g.y; v.z *= g.z; v.w *= g.w;
        __stcs(&o4[(long)c * HW4_ + p], v);
    }
}

// ---------------------------------------------------------------------------
extern "C" void kernel_launch(void* const* d_in, const int* in_sizes, int n_in,
                              void* d_out, int out_size) {
    const float* x      = (const float*)d_in[0];
    const float* conv_w = (const float*)d_in[1];
    const float* conv_b = (const float*)d_in[2];
    float* out = (float*)d_out;

    // allow >48KB dynamic smem (host-side attribute, idempotent, graph-safe)
    cudaFuncSetAttribute(fused_pipe_kernel,
                         cudaFuncAttributeMaxDynamicSharedMemorySize, DYN_SMEM);

    reset_flags_kernel<<<(B_ * H_ + 255) / 256, 256>>>();

    fused_pipe_kernel<<<B_ * H_, 256, DYN_SMEM>>>(x, conv_w, conv_b, out);
}

// round 8
// speedup vs baseline: 1.0807x; 1.0807x over previous
#include <cuda_runtime.h>
#include <math.h>

// Problem constants
#define B_    16
#define C_    64
#define H_    224
#define W_    224
#define HW_   (H_ * W_)          // 50176
#define HW4_  (HW_ / 4)          // 12544
#define CHW4_ ((C_ * HW_) / 4)   // 802816
#define ROW4  56                 // float4 per row

// Device-global scratch (no allocation allowed)
__device__ float g_avg[B_ * HW_];            // 3.2 MB
__device__ float g_max[B_ * HW_];            // 3.2 MB
__device__ unsigned int g_flags[B_ * H_];    // per-row "feat ready" flags

// ---------------------------------------------------------------------------
// Kernel 0: reset flags (device globals persist across graph replays).
// ---------------------------------------------------------------------------
__global__ void reset_flags_kernel() {
    int i = blockIdx.x * blockDim.x + threadIdx.x;
    if (i < B_ * H_) g_flags[i] = 0u;
}

// ---------------------------------------------------------------------------
// Main kernel: one CTA = (batch, row). 448 threads = (slice s 0..7, pos p 0..55).
// Thread caches its 8 channels' float4 in REGISTERS; x read from DRAM once,
// never re-read, never through smem. Cross-row feat dependency via flags.
// ---------------------------------------------------------------------------
__global__ void __launch_bounds__(448, 2) fused_row_kernel(
        const float* __restrict__ x,
        const float* __restrict__ conv_w,
        const float* __restrict__ conv_b,
        float* __restrict__ out) {
    __shared__ float4 scr4[896];        // 14336B: psum [0..447] pmax [448..895]; later halo
    __shared__ float4 s_gate4[56];      // 224 gates
    __shared__ float  s_part[2][224];   // conv channel partials
    __shared__ float  s_w[98];

    int t   = threadIdx.x;              // 0..447
    int bid = blockIdx.x;
    int b   = bid / H_;
    int h   = bid - b * H_;

    if (t < 98) s_w[t] = conv_w[t];

    int s = t / ROW4;                   // channel slice 0..7
    int p = t - s * ROW4;               // float4 position 0..55

    const float4* xb = (const float4*)x
                     + (long)b * CHW4_ + (long)(s * 8) * HW4_ + h * ROW4 + p;

    // ---- Phase 1: load 8 channels into registers (evict-first; no reuse) ----
    float4 v0 = __ldcs(xb + 0L * HW4_);
    float4 v1 = __ldcs(xb + 1L * HW4_);
    float4 v2 = __ldcs(xb + 2L * HW4_);
    float4 v3 = __ldcs(xb + 3L * HW4_);
    float4 v4 = __ldcs(xb + 4L * HW4_);
    float4 v5 = __ldcs(xb + 5L * HW4_);
    float4 v6 = __ldcs(xb + 6L * HW4_);
    float4 v7 = __ldcs(xb + 7L * HW4_);

    float4 sum, mx;
    sum.x = v0.x + v1.x + v2.x + v3.x + v4.x + v5.x + v6.x + v7.x;
    sum.y = v0.y + v1.y + v2.y + v3.y + v4.y + v5.y + v6.y + v7.y;
    sum.z = v0.z + v1.z + v2.z + v3.z + v4.z + v5.z + v6.z + v7.z;
    sum.w = v0.w + v1.w + v2.w + v3.w + v4.w + v5.w + v6.w + v7.w;
    mx.x = fmaxf(fmaxf(fmaxf(v0.x, v1.x), fmaxf(v2.x, v3.x)),
                 fmaxf(fmaxf(v4.x, v5.x), fmaxf(v6.x, v7.x)));
    mx.y = fmaxf(fmaxf(fmaxf(v0.y, v1.y), fmaxf(v2.y, v3.y)),
                 fmaxf(fmaxf(v4.y, v5.y), fmaxf(v6.y, v7.y)));
    mx.z = fmaxf(fmaxf(fmaxf(v0.z, v1.z), fmaxf(v2.z, v3.z)),
                 fmaxf(fmaxf(v4.z, v5.z), fmaxf(v6.z, v7.z)));
    mx.w = fmaxf(fmaxf(fmaxf(v0.w, v1.w), fmaxf(v2.w, v3.w)),
                 fmaxf(fmaxf(v4.w, v5.w), fmaxf(v6.w, v7.w)));
    scr4[s * ROW4 + p]       = sum;
    scr4[448 + s * ROW4 + p] = mx;
    __syncthreads();

    // finalize feat row (56 threads) -> global (normal stores: keep L2-hot)
    if (t < ROW4) {
        float4 a = scr4[t];
        float4 m = scr4[448 + t];
#pragma unroll
        for (int q = 1; q < 8; q++) {
            float4 a2 = scr4[q * ROW4 + t];
            float4 m2 = scr4[448 + q * ROW4 + t];
            a.x += a2.x; a.y += a2.y; a.z += a2.z; a.w += a2.w;
            m.x = fmaxf(m.x, m2.x); m.y = fmaxf(m.y, m2.y);
            m.z = fmaxf(m.z, m2.z); m.w = fmaxf(m.w, m2.w);
        }
        const float inv = 1.0f / (float)C_;
        a.x *= inv; a.y *= inv; a.z *= inv; a.w *= inv;
        ((float4*)g_avg)[b * HW4_ + h * ROW4 + t] = a;
        ((float4*)g_max)[b * HW4_ + h * ROW4 + t] = m;
    }
    __syncthreads();
    if (t == 0) {
        __threadfence();
        atomicExch(&g_flags[bid], 1u);
    }

    // ---- Phase 2: wait for neighbor feat rows (h-3..h+3) ----
    if (t < 7 && t != 3) {
        int hh = h - 3 + t;
        if (hh >= 0 && hh < H_) {
            while (atomicAdd(&g_flags[b * H_ + hh], 0u) == 0u)
                __nanosleep(64);
            __threadfence();            // acquire
        }
    }
    __syncthreads();

    // ---- Phase 3: halo (2ch x 7r x 230c) + split 7x7 conv + sigmoid ----
    float* halo = (float*)scr4;         // reuse; 3248 floats <= 3584
    for (int i = t; i < 2 * 7 * 230; i += 448) {
        int ch = i / 1610;
        int rr = i - ch * 1610;
        int r  = rr / 230;
        int hc = rr - r * 230;
        int hh = h - 3 + r;
        int gw = hc - 3;
        float fv = 0.f;
        if (hh >= 0 && hh < H_ && gw >= 0 && gw < W_)
            fv = (ch ? g_max : g_avg)[b * HW_ + hh * W_ + gw];
        halo[(ch * 7 + r) * 232 + hc] = fv;
    }
    __syncthreads();

    {   // each thread: one (channel, gate-col) partial — all 448 threads busy
        int ch = t / 224;
        int gw = t - ch * 224;
        float acc = 0.f;
        const float* hb = halo + ch * 7 * 232 + gw;
        const float* wb = s_w + ch * 49;
#pragma unroll
        for (int kh = 0; kh < 7; kh++) {
            const float* rp = hb + kh * 232;
            const float* wk = wb + kh * 7;
#pragma unroll
            for (int kw = 0; kw < 7; kw++)
                acc = fmaf(rp[kw], wk[kw], acc);
        }
        s_part[ch][gw] = acc;
    }
    __syncthreads();
    if (t < 224) {
        float a = s_part[0][t] + s_part[1][t] + conv_b[0];
        ((float*)s_gate4)[t] = 1.0f / (1.0f + __expf(-a));
    }
    __syncthreads();

    // ---- Phase 4: multiply register-cached x by gate, stream out ----
    float4 g = s_gate4[p];
    float4* ob = (float4*)out
               + (long)b * CHW4_ + (long)(s * 8) * HW4_ + h * ROW4 + p;
    v0.x *= g.x; v0.y *= g.y; v0.z *= g.z; v0.w *= g.w; __stcs(ob + 0L * HW4_, v0);
    v1.x *= g.x; v1.y *= g.y; v1.z *= g.z; v1.w *= g.w; __stcs(ob + 1L * HW4_, v1);
    v2.x *= g.x; v2.y *= g.y; v2.z *= g.z; v2.w *= g.w; __stcs(ob + 2L * HW4_, v2);
    v3.x *= g.x; v3.y *= g.y; v3.z *= g.z; v3.w *= g.w; __stcs(ob + 3L * HW4_, v3);
    v4.x *= g.x; v4.y *= g.y; v4.z *= g.z; v4.w *= g.w; __stcs(ob + 4L * HW4_, v4);
    v5.x *= g.x; v5.y *= g.y; v5.z *= g.z; v5.w *= g.w; __stcs(ob + 5L * HW4_, v5);
    v6.x *= g.x; v6.y *= g.y; v6.z *= g.z; v6.w *= g.w; __stcs(ob + 6L * HW4_, v6);
    v7.x *= g.x; v7.y *= g.y; v7.z *= g.z; v7.w *= g.w; __stcs(ob + 7L * HW4_, v7);
}

// ---------------------------------------------------------------------------
extern "C" void kernel_launch(void* const* d_in, const int* in_sizes, int n_in,
                              void* d_out, int out_size) {
    const float* x      = (const float*)d_in[0];
    const float* conv_w = (const float*)d_in[1];
    const float* conv_b = (const float*)d_in[2];
    float* out = (float*)d_out;

    reset_flags_kernel<<<(B_ * H_ + 255) / 256, 256>>>();
    fused_row_kernel<<<B_ * H_, 448>>>(x, conv_w, conv_b, out);
}

// round 9
// speedup vs baseline: 1.2306x; 1.1387x over previous
#include <cuda_runtime.h>
#include <math.h>

// Problem constants
#define B_    16
#define C_    64
#define H_    224
#define W_    224
#define HW_   (H_ * W_)          // 50176
#define CHW_  (C_ * HW_)         // 3211264
#define HW4_  (HW_ / 4)          // 12544
#define CHW4_ (CHW_ / 4)         // 802816

// Scratch (device globals — no allocation allowed)
__device__ float g_avg[B_ * HW_];   // 3.2 MB
__device__ float g_max[B_ * HW_];   // 3.2 MB

// ---------------------------------------------------------------------------
// Kernel 1: channel-wise mean + max reduce (proven at roofline: ~33us, 80%).
// One thread = 4 consecutive w positions; 64 channel-strided LDG.128.
// ---------------------------------------------------------------------------
__global__ void reduce_kernel(const float* __restrict__ x) {
    int idx = blockIdx.x * blockDim.x + threadIdx.x;   // float4 idx in [0, B_*HW4_)
    if (idx >= B_ * HW4_) return;
    int b = idx / HW4_;
    int p = idx - b * HW4_;

    const float4* x4 = (const float4*)x;
    long base = (long)b * CHW4_ + p;

    float4 s = make_float4(0.f, 0.f, 0.f, 0.f);
    float4 m = make_float4(-INFINITY, -INFINITY, -INFINITY, -INFINITY);

#pragma unroll 8
    for (int c = 0; c < C_; c++) {
        float4 v = x4[base + (long)c * HW4_];
        s.x += v.x; s.y += v.y; s.z += v.z; s.w += v.w;
        m.x = fmaxf(m.x, v.x); m.y = fmaxf(m.y, v.y);
        m.z = fmaxf(m.z, v.z); m.w = fmaxf(m.w, v.w);
    }
    const float inv = 1.0f / (float)C_;
    s.x *= inv; s.y *= inv; s.z *= inv; s.w *= inv;

    ((float4*)g_avg)[idx] = s;     // normal stores: keep feat L2-hot for K2
    ((float4*)g_max)[idx] = m;
}

// ---------------------------------------------------------------------------
// Kernel 2 (fused): conv7x7 + sigmoid -> gate (registers) -> out = x * gate.
// BAND=4 rows per CTA -> 1792 CTAs (~2+ waves): wave-2 prologues hide under
// wave-1 streaming; tail smooths. Thread t owns float4 at (row=t/56, w=4*(t%56)),
// holds its gate in a register across the 64-channel multiply loop.
// ---------------------------------------------------------------------------
#define BAND  4                 // output rows per CTA
#define HR    10                // BAND + 6 halo rows
#define HC    230               // 224 + 6 halo cols
#define HCP   232               // padded row stride (16B-aligned rows)

__global__ void __launch_bounds__(224) fused_gate_mul_kernel(
        const float* __restrict__ x,
        const float* __restrict__ conv_w,
        const float* __restrict__ conv_b,
        float* __restrict__ out) {
    __shared__ float s_feat[2 * HR * HCP];   // 18.6 KB
    __shared__ float s_w[98];

    int t  = threadIdx.x;            // 0..223
    int h0 = blockIdx.x * BAND;      // 56 bands (adjacent bands -> adjacent bids)
    int b  = blockIdx.y;             // 16 batches

    if (t < 98) s_w[t] = conv_w[t];

    // Halo load: 2 ch x 10 rows x 230 cols = 4600 elements (L2-hot feat)
    const float* srcA = g_avg + b * HW_;
    const float* srcM = g_max + b * HW_;
    for (int i = t; i < 2 * HR * HC; i += 224) {
        int ch = i / (HR * HC);
        int rr = i - ch * (HR * HC);
        int r  = rr / HC;
        int cc = rr - r * HC;
        int gh = h0 + r - 3;
        int gw = cc - 3;
        float v = 0.f;
        if (gh >= 0 && gh < H_ && gw >= 0 && gw < W_)
            v = __ldg((ch == 0 ? srcA : srcM) + gh * W_ + gw);
        s_feat[ch * HR * HCP + r * HCP + cc] = v;
    }
    __syncthreads();

    int row = t / 56;                // 0..3
    int w4  = t - row * 56;          // 0..55  (w = 4*w4)

    // Phase 1: 7x7 conv over 2 channels for this thread's 4 outputs
    float a0 = conv_b[0], a1 = a0, a2 = a0, a3 = a0;
#pragma unroll
    for (int ch = 0; ch < 2; ch++) {
#pragma unroll
        for (int kh = 0; kh < 7; kh++) {
            const float* rp = s_feat + ch * HR * HCP + (row + kh) * HCP + 4 * w4;
            float4 v0 = *(const float4*)(rp);       // LDS.128 (16B-aligned)
            float4 v1 = *(const float4*)(rp + 4);
            float  e0 = rp[8];
            float  e1 = rp[9];
            float r_[10] = { v0.x, v0.y, v0.z, v0.w,
                             v1.x, v1.y, v1.z, v1.w, e0, e1 };
            const float* wk = s_w + ch * 49 + kh * 7;
#pragma unroll
            for (int kw = 0; kw < 7; kw++) {
                float wv = wk[kw];
                a0 = fmaf(r_[kw + 0], wv, a0);
                a1 = fmaf(r_[kw + 1], wv, a1);
                a2 = fmaf(r_[kw + 2], wv, a2);
                a3 = fmaf(r_[kw + 3], wv, a3);
            }
        }
    }

    float4 g;
    g.x = 1.0f / (1.0f + __expf(-a0));
    g.y = 1.0f / (1.0f + __expf(-a1));
    g.z = 1.0f / (1.0f + __expf(-a2));
    g.w = 1.0f / (1.0f + __expf(-a3));

    // Phase 2: multiply own float4 across all 64 channels (LDG/STG.128)
    long base4 = (long)b * CHW4_ + (h0 + row) * 56 + w4;
    const float4* x4 = (const float4*)x;
    float4* o4 = (float4*)out;

#pragma unroll 8
    for (int c = 0; c < C_; c++) {
        long idx = base4 + (long)c * HW4_;
        float4 v = x4[idx];
        v.x *= g.x; v.y *= g.y; v.z *= g.z; v.w *= g.w;
        __stcs(o4 + idx, v);
    }
}

// ---------------------------------------------------------------------------
extern "C" void kernel_launch(void* const* d_in, const int* in_sizes, int n_in,
                              void* d_out, int out_size) {
    const float* x      = (const float*)d_in[0];
    const float* conv_w = (const float*)d_in[1];
    const float* conv_b = (const float*)d_in[2];
    float* out = (float*)d_out;

    // K1: channel reduce over full tensor (at DRAM roofline)
    {
        int n = B_ * HW4_;                   // 200704 threads
        reduce_kernel<<<(n + 255) / 256, 256>>>(x);
    }
    // K2: fused conv + sigmoid + broadcast multiply (fine-grained grid)
    {
        dim3 grd(H_ / BAND, B_);             // (56, 16) = 1792 CTAs
        fused_gate_mul_kernel<<<grd, 224>>>(x, conv_w, conv_b, out);
    }
}